// round 6
// baseline (speedup 1.0000x reference)
#include <cuda_runtime.h>
#include <stdint.h>

#define NEGF (-1e30f)

constexpr int T = 1024;
constexpr int B = 32;
constexpr int C = 96;
constexpr int W = 16;   // beam width
constexpr int P = 4;    // top paths
constexpr int S = 17;   // top lp columns kept per (b,t): 16 non-demoted + 1 => exact

// per (b,t): top-S non-blank lp columns as packed keys (ord(lp)<<7 | (127-c)), desc
__device__ unsigned long long g_sorted[(size_t)B * T * S];

// ---------- key helpers ----------
__device__ __forceinline__ unsigned ford(float f) {
    unsigned u = __float_as_uint(f);
    return (u & 0x80000000u) ? ~u : (u | 0x80000000u);
}
__device__ __forceinline__ float funord(unsigned ord) {
    unsigned u = (ord & 0x80000000u) ? (ord ^ 0x80000000u) : ~ord;
    return __uint_as_float(u);
}
// larger score wins; ties -> lower global index wins (matches jax.lax.top_k)
__device__ __forceinline__ unsigned long long make_key(float f, int idx) {
    return ((unsigned long long)ford(f) << 11) | (unsigned long long)(2047 - idx);
}
__device__ __forceinline__ int key_idx(unsigned long long k) { return 2047 - (int)(k & 2047ULL); }
__device__ __forceinline__ float key_score(unsigned long long k) { return funord((unsigned)(k >> 11)); }

__device__ __forceinline__ float lae(float a, float b) {   // jnp.logaddexp
    float m = fmaxf(a, b);
    float d = fabsf(a - b);
    return m + log1pf(expf(-d));
}
__device__ __forceinline__ unsigned long long warp_max(unsigned long long v) {
    #pragma unroll
    for (int o = 16; o; o >>= 1) {
        unsigned long long w = __shfl_xor_sync(0xffffffffu, v, o);
        v = (w > v) ? w : v;
    }
    return v;
}

// ============================================================================
// Kernel 1: per-(b,t) bitonic sort of non-blank lp columns, keep top-S.
// ============================================================================
__global__ __launch_bounds__(256)
void presort_kernel(const float* __restrict__ data)   // [T, B, C]
{
    int warp = (blockIdx.x * blockDim.x + threadIdx.x) >> 5;
    if (warp >= B * T) return;
    int b = warp / T, t = warp - b * T;
    int lane = threadIdx.x & 31;

    const float* row = data + ((size_t)t * B + b) * C;
    unsigned long long k[4];
    #pragma unroll
    for (int r = 0; r < 4; ++r) {
        int c = r * 32 + lane;
        if (c >= 1 && c < C)
            k[r] = ((unsigned long long)ford(row[c]) << 7) | (unsigned long long)(127 - c);
        else
            k[r] = 0ULL;
    }
    #pragma unroll
    for (int k2 = 2; k2 <= 128; k2 <<= 1) {
        #pragma unroll
        for (int j = 64; j > 0; j >>= 1) {
            if (j >= k2) continue;
            if (j >= 32) {
                int rj = j >> 5;
                #pragma unroll
                for (int r = 0; r < 4; ++r) {
                    if ((r & rj) == 0) {
                        int pr = r | rj;
                        bool desc = (((r * 32) & k2) == 0);
                        unsigned long long a = k[r], c2 = k[pr];
                        unsigned long long mx = a > c2 ? a : c2;
                        unsigned long long mn = a > c2 ? c2 : a;
                        k[r]  = desc ? mx : mn;
                        k[pr] = desc ? mn : mx;
                    }
                }
            } else {
                #pragma unroll
                for (int r = 0; r < 4; ++r) {
                    unsigned long long o = __shfl_xor_sync(0xffffffffu, k[r], j);
                    int e = r * 32 + lane;
                    bool takemax = ((e & k2) == 0) == ((lane & j) == 0);
                    bool bigger  = k[r] > o;
                    k[r] = (takemax == bigger) ? k[r] : o;
                }
            }
        }
    }
    if (lane < S)
        g_sorted[((size_t)b * T + t) * S + lane] = k[0];
}

// ============================================================================
// Kernel 2: sequential beam search, one CTA per batch element.
//  phase1 (16 warps): stay/rep keys + lae computed HERE (overlaps shuffles);
//  merge segment: warp 0 does pure-select merge+update while warps 4-8 park
//  the 2-deep prefetched next row (DRAM latency fully hidden).
// ============================================================================
__global__ __launch_bounds__(512, 1)
void ctc_beam_kernel(const float* __restrict__ data,      // [T, B, C]
                     const int*   __restrict__ data_len,  // [B]
                     float*       __restrict__ out)
{
    const int b    = blockIdx.x;
    const int tid  = threadIdx.x;
    const int lane = tid & 31;
    const int wid  = tid >> 5;
    const int len  = data_len[b];
    const unsigned FULL = 0xffffffffu;

    __shared__ float sh_lp[2][C];
    __shared__ unsigned long long sh_srt[2][S];
    __shared__ float sf_pb[W], sf_pnb[W], sf_ptot[W], sf_spb[W], sf_spnb[W];
    __shared__ int   sf_last[W], sf_len[W];
    __shared__ unsigned long long s_top[W][W];
    __shared__ unsigned short s_bp[T][W];                 // (parent<<8)|sym, 0xFF = stay
    __shared__ int   s_selslot[P], s_sellen[P];
    __shared__ float s_selscore[P];

    // prefetch owners: warps 4-6 own lp (96 threads), warp 8 owns srt (17 threads)
    const bool lp_owner = (tid >= 128 && tid < 128 + C);
    const int  lpc      = tid - 128;
    const bool sr_owner = (tid >= 256 && tid < 256 + S);
    const int  src      = tid - 256;

    // prologue: row 0 direct to SMEM; row 1 issued into slot B
    if (lp_owner) sh_lp[0][lpc] = data[(size_t)b * C + lpc];
    if (sr_owner) sh_srt[0][src] = g_sorted[((size_t)b * T) * S + src];
    float preA = 0.0f, preB = 0.0f;
    unsigned long long psA = 0ULL, psB = 0ULL;
    if (lp_owner) preB = data[(size_t)(B + b) * C + lpc];            // row 1
    if (sr_owner) psB  = g_sorted[((size_t)b * T + 1) * S + src];

    if (tid < W) {
        float pb0 = (tid == 0) ? 0.0f : NEGF;
        sf_pb[tid]   = pb0;
        sf_pnb[tid]  = NEGF;
        sf_ptot[tid] = lae(pb0, NEGF);
        sf_last[tid] = -1;
        sf_len[tid]  = 0;
    }
    __syncthreads();

    for (int t = 0; t < len; ++t) {
        const int buf = t & 1, nb = buf ^ 1;

        // issue LDG for row t+2 (2-deep pipeline; parked next iteration)
        if (t + 2 < T) {
            if ((t & 1) == 0) {
                if (lp_owner) preA = data[(size_t)((t + 2) * B + b) * C + lpc];
                if (sr_owner) psA  = g_sorted[((size_t)b * T + t + 2) * S + src];
            } else {
                if (lp_owner) preB = data[(size_t)((t + 2) * B + b) * C + lpc];
                if (sr_owner) psB  = g_sorted[((size_t)b * T + t + 2) * S + src];
            }
        }

        // -------- phase 1: warp w emits its sorted top-16 (no sort) --------
        {
            const int w = wid;
            float ptw   = sf_ptot[w];
            float pbw   = sf_pb[w];
            float pnbw  = sf_pnb[w];
            int   lastw = sf_last[w];
            int   lenw  = sf_len[w];

            float lp0 = sh_lp[buf][0];
            float lpl = sh_lp[buf][(lenw > 0) ? lastw : 0];
            float spb  = ptw + lp0;
            float spnb = (lenw > 0) ? (pnbw + lpl) : NEGF;
            if (lane == 0) { sf_spb[w] = spb; sf_spnb[w] = spnb; }
            // lae overlaps with the shuffle passes below (independent chains)
            unsigned long long stayk = make_key(lae(spb, spnb), w);
            unsigned long long repk  = (lenw > 0)
                ? make_key(pbw + lpl, W + w * C + lastw) : 0ULL;

            unsigned long long key = 0ULL; int c = -2;
            if (lane < S) {
                unsigned long long sk = sh_srt[buf][lane];
                c = 127 - (int)(sk & 127ULL);
                key = make_key(funord((unsigned)(sk >> 7)) + ptw, W + w * C + c);
            }
            // odd-even cleanup pass A: pairs (0,1),(2,3),...
            {
                unsigned long long ok = __shfl_xor_sync(FULL, key, 1);
                int oc = __shfl_xor_sync(FULL, c, 1);
                bool keep_hi = (lane & 1) == 0;
                if (lane < S && (keep_hi != (key > ok))) { key = ok; c = oc; }
            }
            // pass B: pairs (1,2),(3,4),...,(15,16)
            {
                int partner = (lane == 0) ? 0 : (lane + ((lane & 1) ? 1 : -1));
                unsigned long long ok = __shfl_sync(FULL, key, partner);
                int oc = __shfl_sync(FULL, c, partner);
                bool keep_hi = (lane & 1) == 1;
                if (lane >= 1 && lane < S && (keep_hi != (key > ok))) { key = ok; c = oc; }
            }
            // drop (undemoted) c==last cell; rank-insert repk & stayk via ballots
            unsigned pm = __ballot_sync(FULL, (lane < S) && (c == lastw));
            bool matched = pm != 0u;
            int  p0 = __ffs(pm) - 1;
            bool is_stat = (lane < S) && !(matched && lane == p0);
            unsigned gb_rep  = __ballot_sync(FULL, is_stat && (key > repk));
            unsigned gb_stay = __ballot_sync(FULL, is_stat && (key > stayk));
            if (is_stat) {
                int r = lane - ((matched && lane > p0) ? 1 : 0)
                      + ((repk  > key) ? 1 : 0) + ((stayk > key) ? 1 : 0);
                if (r < W) s_top[w][r] = key;
            }
            if (lane == 0) {
                int rr = __popc(gb_rep)  + ((stayk > repk)  ? 1 : 0);
                int rs = __popc(gb_stay) + ((repk  > stayk) ? 1 : 0);
                if (rr < W) s_top[w][rr] = repk;
                if (rs < W) s_top[w][rs] = stayk;
            }
        }
        __syncthreads();   // bar1: s_top + sf_spb/spnb visible

        if (wid == 0) {
            // -------- merge 16 sorted 16-lists (pure select, no lae) --------
            unsigned long long m[8];
            const int rr = lane & 15, h = lane >> 4;
            #pragma unroll
            for (int q = 0; q < 8; ++q) m[q] = s_top[2 * q + h][rr];
            #pragma unroll
            for (int lvl = 0; lvl < 4; ++lvl) {
                const int nreg = 8 >> lvl;
                #pragma unroll
                for (int q = 0; q < 8; ++q) {
                    if (q >= nreg) break;
                    unsigned long long o = __shfl_xor_sync(FULL, m[q], 31);
                    unsigned long long v = (m[q] > o) ? m[q] : o;
                    #pragma unroll
                    for (int j = 8; j > 0; j >>= 1) {
                        unsigned long long o2 = __shfl_xor_sync(FULL, v, j);
                        bool takemax = ((lane & j) == 0);
                        bool bigger  = v > o2;
                        v = (takemax == bigger) ? v : o2;
                    }
                    m[q] = v;
                }
                #pragma unroll
                for (int q = 0; q < 4; ++q) {
                    if (q >= (nreg >> 1)) break;
                    m[q] = (lane < 16) ? m[2 * q] : m[2 * q + 1];
                }
            }

            // decode rank-lane winner, update replicated beam state in SMEM
            unsigned long long win = m[0];
            int   idx   = key_idx(win);
            float score = key_score(win);
            bool  is_stay = idx < W;
            int   e = is_stay ? 0 : (idx - W);
            int   epar = e / C;
            int   csym = e - epar * C;
            int   parent = (is_stay ? idx : epar) & 15;
            float p_spb  = sf_spb[parent];
            float p_spnb = sf_spnb[parent];
            int   p_len  = sf_len[parent];
            int   p_last = sf_last[parent];

            float npb   = is_stay ? p_spb  : NEGF;
            float npnb  = is_stay ? p_spnb : score;
            int   nlen  = is_stay ? p_len  : (p_len + 1);
            int   nlast = is_stay ? p_last : csym;

            if (lane < W) {
                sf_pb[lane]   = npb;
                sf_pnb[lane]  = npnb;
                sf_ptot[lane] = score;       // == lae(npb, npnb) bit-exactly
                sf_last[lane] = nlast;
                sf_len[lane]  = nlen;
                s_bp[t][lane] = (unsigned short)((parent << 8) | (is_stay ? 0xFF : csym));
            }
        } else if (t + 1 < T) {
            // -------- park prefetched row t+1 (in flight a full iteration) --------
            if ((t & 1) == 0) {
                if (lp_owner) sh_lp[nb][lpc] = preB;
                if (sr_owner) sh_srt[nb][src] = psB;
            } else {
                if (lp_owner) sh_lp[nb][lpc] = preA;
                if (sr_owner) sh_srt[nb][src] = psA;
            }
        }
        __syncthreads();   // bar2: new state + next row visible
    }

    // -------- final top-P over total beam probabilities --------
    if (wid == 0) {
        unsigned long long key = (lane < W) ? make_key(sf_ptot[lane], lane) : 0ULL;
        #pragma unroll
        for (int r = 0; r < P; ++r) {
            unsigned long long win = warp_max(key);
            if (key == win) key = 0ULL;
            int slot = key_idx(win) & 15;
            if (lane == 0) {
                s_selslot[r]  = slot;
                s_selscore[r] = key_score(win);
                s_sellen[r]   = sf_len[slot];
            }
        }
    }
    __syncthreads();

    // -------- outputs (flattened float32): -scores, lens, labels --------
    float* o_neg = out;
    float* o_len = out + B * P;
    float* o_dec = out + 2 * B * P;

    if (tid < P) {
        o_neg[b * P + tid] = -s_selscore[tid];
        o_len[b * P + tid] = (float)s_sellen[tid];
    }
    for (int i = tid; i < P * T; i += blockDim.x)
        o_dec[(size_t)b * P * T + i] = -1.0f;
    __syncthreads();

    if (tid < P) {
        int slot = s_selslot[tid];
        int pos  = s_sellen[tid];
        float* dst = o_dec + ((size_t)b * P + tid) * T;
        for (int tt = len - 1; tt >= 0; --tt) {
            unsigned e = s_bp[tt][slot];
            int sym = e & 0xFF;
            slot    = e >> 8;
            if (sym != 0xFF) dst[--pos] = (float)sym;
        }
    }
}

extern "C" void kernel_launch(void* const* d_in, const int* in_sizes, int n_in,
                              void* d_out, int out_size) {
    const float* data = (const float*)d_in[0];
    const int*   dlen = (const int*)d_in[1];
    presort_kernel<<<(B * T + 7) / 8, 256>>>(data);
    ctc_beam_kernel<<<B, 512>>>(data, dlen, (float*)d_out);
}

// round 7
// speedup vs baseline: 1.4904x; 1.4904x over previous
#include <cuda_runtime.h>
#include <stdint.h>

#define NEGF (-1e30f)

constexpr int T = 1024;
constexpr int B = 32;
constexpr int C = 96;
constexpr int W = 16;   // beam width
constexpr int P = 4;    // top paths
constexpr int S = 21;   // top lp columns kept per (b,t); staircase needs i <= 20

// per (b,t): top-S non-blank lp columns as packed keys (ord(lp)<<7 | (127-c)), desc
__device__ unsigned long long g_sorted[(size_t)B * T * S];

// ---------- key helpers ----------
__device__ __forceinline__ unsigned ford(float f) {
    unsigned u = __float_as_uint(f);
    return (u & 0x80000000u) ? ~u : (u | 0x80000000u);
}
__device__ __forceinline__ float funord(unsigned ord) {
    unsigned u = (ord & 0x80000000u) ? (ord ^ 0x80000000u) : ~ord;
    return __uint_as_float(u);
}
// larger score wins; ties -> lower global index wins (matches jax.lax.top_k)
__device__ __forceinline__ unsigned long long make_key(float f, int idx) {
    return ((unsigned long long)ford(f) << 11) | (unsigned long long)(2047 - idx);
}
__device__ __forceinline__ int key_idx(unsigned long long k) { return 2047 - (int)(k & 2047ULL); }
__device__ __forceinline__ float key_score(unsigned long long k) { return funord((unsigned)(k >> 11)); }

__device__ __forceinline__ float lae(float a, float b) {   // jnp.logaddexp
    float m = fmaxf(a, b);
    float d = fabsf(a - b);
    return m + log1pf(expf(-d));
}

// descending bitonic sort of 32 keys across a warp (lane = index). Proven in R2.
__device__ __forceinline__ void sort32_desc(unsigned long long& v, int lane) {
    #pragma unroll
    for (int k2 = 2; k2 <= 32; k2 <<= 1) {
        #pragma unroll
        for (int j = k2 >> 1; j > 0; j >>= 1) {
            unsigned long long o = __shfl_xor_sync(0xffffffffu, v, j);
            bool takemax = ((lane & k2) == 0) == ((lane & j) == 0);
            bool bigger  = v > o;
            v = (takemax == bigger) ? v : o;
        }
    }
}

// top-16 (sorted desc, lanes 0-15) of two lists whose top-16 live sorted-desc
// in lanes 0-15 of a and b. Mirror-max + 4-pass bitonic clean. Proven in R4/R5.
__device__ __forceinline__ unsigned long long merge_top16(
    unsigned long long a, unsigned long long b, int lane) {
    unsigned long long brev = __shfl_sync(0xffffffffu, b, (15 - lane) & 31);
    unsigned long long v = (a > brev) ? a : brev;
    #pragma unroll
    for (int j = 8; j > 0; j >>= 1) {
        unsigned long long o = __shfl_xor_sync(0xffffffffu, v, j);
        bool takemax = ((lane & j) == 0);
        bool bigger  = v > o;
        v = (takemax == bigger) ? v : o;
    }
    return v;   // lanes 0-15 valid
}

// ============================================================================
// Kernel 1: per-(b,t) bitonic sort of non-blank lp columns, keep top-S.
// ============================================================================
__global__ __launch_bounds__(256)
void presort_kernel(const float* __restrict__ data)   // [T, B, C]
{
    int warp = (blockIdx.x * blockDim.x + threadIdx.x) >> 5;
    if (warp >= B * T) return;
    int b = warp / T, t = warp - b * T;
    int lane = threadIdx.x & 31;

    const float* row = data + ((size_t)t * B + b) * C;
    unsigned long long k[4];
    #pragma unroll
    for (int r = 0; r < 4; ++r) {
        int c = r * 32 + lane;
        if (c >= 1 && c < C)
            k[r] = ((unsigned long long)ford(row[c]) << 7) | (unsigned long long)(127 - c);
        else
            k[r] = 0ULL;
    }
    #pragma unroll
    for (int k2 = 2; k2 <= 128; k2 <<= 1) {
        #pragma unroll
        for (int j = 64; j > 0; j >>= 1) {
            if (j >= k2) continue;
            if (j >= 32) {
                int rj = j >> 5;
                #pragma unroll
                for (int r = 0; r < 4; ++r) {
                    if ((r & rj) == 0) {
                        int pr = r | rj;
                        bool desc = (((r * 32) & k2) == 0);
                        unsigned long long a = k[r], c2 = k[pr];
                        unsigned long long mx = a > c2 ? a : c2;
                        unsigned long long mn = a > c2 ? c2 : a;
                        k[r]  = desc ? mx : mn;
                        k[pr] = desc ? mn : mx;
                    }
                }
            } else {
                #pragma unroll
                for (int r = 0; r < 4; ++r) {
                    unsigned long long o = __shfl_xor_sync(0xffffffffu, k[r], j);
                    int e = r * 32 + lane;
                    bool takemax = ((e & k2) == 0) == ((lane & j) == 0);
                    bool bigger  = k[r] > o;
                    k[r] = (takemax == bigger) ? k[r] : o;
                }
            }
        }
    }
    if (lane < S)
        g_sorted[((size_t)b * T + t) * S + lane] = k[0];
}

// ============================================================================
// Kernel 2: ONE WARP per batch element. Zero barriers, register-resident state.
// Staircase candidate pool (78 ext cells + 16 stay + 16 rep) sorted exactly.
// ============================================================================
__global__ __launch_bounds__(32, 1)
void ctc_beam_kernel(const float* __restrict__ data,      // [T, B, C]
                     const int*   __restrict__ data_len,  // [B]
                     float*       __restrict__ out)
{
    const int b    = blockIdx.x;
    const int lane = threadIdx.x;
    const int len  = data_len[b];
    const unsigned FULL = 0xffffffffu;

    __shared__ float sh_lp[2][C];
    __shared__ unsigned long long sh_srt[2][S];
    __shared__ unsigned short s_bp[T][W];                 // (parent<<8)|sym, 0xFF = stay
    __shared__ int   s_selslot[P], s_sellen[P];
    __shared__ float s_selscore[P];

    // ---- static pool map: slot s = r*32+lane -> (w, i), staircase i <= 20/(w+1)
    // counts per row: {21,11,7,6,5,4,3,3,3,3,2,2,2,2,2,2} -> 78 cells
    int pw[3], pi[3];
    {
        const int pref[17] = {0,21,32,39,45,50,54,57,60,63,66,68,70,72,74,76,78};
        #pragma unroll
        for (int r = 0; r < 3; ++r) {
            int s = r * 32 + lane;
            int w = -1, i = 0;
            #pragma unroll
            for (int ww = 0; ww < 16; ++ww)
                if (s >= pref[ww] && s < pref[ww + 1]) { w = ww; i = s - pref[ww]; }
            pw[r] = w; pi[r] = i;
        }
    }

    // ---- prologue: row 0 into buf 0
    {
        const float* row0 = data + (size_t)b * C;
        sh_lp[0][lane]      = row0[lane];
        sh_lp[0][32 + lane] = row0[32 + lane];
        sh_lp[0][64 + lane] = row0[64 + lane];
        if (lane < S) sh_srt[0][lane] = g_sorted[((size_t)b * T) * S + lane];
    }
    __syncwarp();

    // ---- register beam state (lanes 0-15 live; high lanes pinned dead)
    float pb   = (lane == 0) ? 0.0f : NEGF;
    float pnb  = NEGF;
    float ptot = lae(pb, pnb);
    int   llen = 0, llast = -1;

    for (int t = 0; t < len; ++t) {
        const int buf = t & 1, nb = buf ^ 1;

        // issue loads for row t+1 (parked ~25 shuffle-passes later)
        float f0 = 0.f, f1 = 0.f, f2 = 0.f; unsigned long long sv = 0ULL;
        if (t + 1 < T) {
            const float* rown = data + (size_t)((t + 1) * B + b) * C;
            f0 = rown[lane]; f1 = rown[32 + lane]; f2 = rown[64 + lane];
            if (lane < S) sv = g_sorted[((size_t)b * T + t + 1) * S + lane];
        }

        // ---- build stay / repeat candidates (lane = beam, SIMD; one lae chain)
        float lp0  = sh_lp[buf][0];
        int   lidx = (llen > 0) ? llast : 0;
        lidx = (lidx >= 0 && lidx < C) ? lidx : 0;        // high-lane safety
        float lpl  = sh_lp[buf][lidx];
        float spb  = ptot + lp0;
        float spnb = (llen > 0) ? (pnb + lpl) : NEGF;
        unsigned long long staykey = make_key(lae(spb, spnb), lane);
        unsigned long long repkey  = (llen > 0)
            ? make_key(pb + lpl, W + lane * C + llast) : 0ULL;

        // ---- assemble pool: regs 0-2 = staircase ext cells, reg 3 = stay|rep
        unsigned long long k0, k1, k2, k3;
        {
            unsigned long long kk[3];
            #pragma unroll
            for (int r = 0; r < 3; ++r) {
                int w = pw[r];
                float pt = __shfl_sync(FULL, ptot,  w & 15);
                int   lw = __shfl_sync(FULL, llast, w & 15);
                unsigned long long key = 0ULL;
                if (w >= 0) {
                    unsigned long long e = sh_srt[buf][pi[r]];
                    int c = 127 - (int)(e & 127ULL);
                    if (c != lw)   // demoted cell excluded; covered by repkey
                        key = make_key(funord((unsigned)(e >> 7)) + pt, W + w * C + c);
                }
                kk[r] = key;
            }
            k0 = kk[0]; k1 = kk[1]; k2 = kk[2];
            unsigned long long rk = __shfl_sync(FULL, repkey, lane & 15);
            k3 = (lane < W) ? staykey : rk;
        }

        // ---- exact top-16: 4x sort-32 (ILP) + 3 mirror merges
        sort32_desc(k0, lane);
        sort32_desc(k1, lane);
        sort32_desc(k2, lane);
        sort32_desc(k3, lane);
        unsigned long long m01 = merge_top16(k0, k1, lane);
        unsigned long long m23 = merge_top16(k2, k3, lane);
        unsigned long long fin = merge_top16(m01, m23, lane);   // lanes 0-15: rank-lane

        // park prefetched row
        if (t + 1 < T) {
            sh_lp[nb][lane]      = f0;
            sh_lp[nb][32 + lane] = f1;
            sh_lp[nb][64 + lane] = f2;
            if (lane < S) sh_srt[nb][lane] = sv;
        }
        __syncwarp();

        // ---- state update (all-register, shuffles from parent lanes)
        int   idx   = key_idx(fin);
        float score = key_score(fin);
        bool  is_stay = idx < W;
        int   e2 = is_stay ? 0 : (idx - W);
        int   epar = e2 / C;
        int   csym = e2 - epar * C;
        int   parent = (is_stay ? idx : epar) & 15;
        float p_spb  = __shfl_sync(FULL, spb,   parent);
        float p_spnb = __shfl_sync(FULL, spnb,  parent);
        int   p_len  = __shfl_sync(FULL, llen,  parent);
        int   p_last = __shfl_sync(FULL, llast, parent);

        bool live = lane < W;
        pb    = live ? (is_stay ? p_spb  : NEGF)        : NEGF;
        pnb   = live ? (is_stay ? p_spnb : score)       : NEGF;
        ptot  = live ? score                            : NEGF;
        llen  = live ? (is_stay ? p_len  : p_len + 1)   : 0;
        llast = live ? (is_stay ? p_last : csym)        : -1;

        if (live)
            s_bp[t][lane] = (unsigned short)((parent << 8) | (is_stay ? 0xFF : csym));
    }

    // ---- final top-P over total beam probabilities
    {
        unsigned long long key = (lane < W) ? make_key(ptot, lane) : 0ULL;
        #pragma unroll
        for (int r = 0; r < P; ++r) {
            unsigned long long v = key;
            #pragma unroll
            for (int o = 16; o; o >>= 1) {
                unsigned long long w2 = __shfl_xor_sync(FULL, v, o);
                v = (w2 > v) ? w2 : v;
            }
            if (key == v) key = 0ULL;
            int slot = key_idx(v) & 15;
            int sl = __shfl_sync(FULL, llen, slot);
            if (lane == 0) {
                s_selslot[r]  = slot;
                s_selscore[r] = key_score(v);
                s_sellen[r]   = sl;
            }
        }
    }
    __syncwarp();

    // ---- outputs (flattened float32): -scores, lens, labels
    float* o_neg = out;
    float* o_len = out + B * P;
    float* o_dec = out + 2 * B * P;

    if (lane < P) {
        o_neg[b * P + lane] = -s_selscore[lane];
        o_len[b * P + lane] = (float)s_sellen[lane];
    }
    for (int i = lane; i < P * T; i += 32)
        o_dec[(size_t)b * P * T + i] = -1.0f;
    __syncwarp();

    if (lane < P) {
        int slot = s_selslot[lane];
        int pos  = s_sellen[lane];
        float* dst = o_dec + ((size_t)b * P + lane) * T;
        for (int tt = len - 1; tt >= 0; --tt) {
            unsigned e = s_bp[tt][slot];
            int sym = e & 0xFF;
            slot    = e >> 8;
            if (sym != 0xFF) dst[--pos] = (float)sym;
        }
    }
}

extern "C" void kernel_launch(void* const* d_in, const int* in_sizes, int n_in,
                              void* d_out, int out_size) {
    const float* data = (const float*)d_in[0];
    const int*   dlen = (const int*)d_in[1];
    presort_kernel<<<(B * T + 7) / 8, 256>>>(data);
    ctc_beam_kernel<<<B, 32>>>(data, dlen, (float*)d_out);
}